// round 7
// baseline (speedup 1.0000x reference)
#include <cuda_runtime.h>
#include <math.h>

#define HDIM 4096
#define IDIM 4096
#define TPB  256
#define NWARP (TPB / 32)
#define ROWS_PER_CTA 2
#define GRID (HDIM / ROWS_PER_CTA)   // 2048

struct Batch {
    float4 x0, h0, x1, h1;
    float4 a0, a1, a2, a3, c0, c1, c2, c3;   // slice A weights
    float4 d0, d1, d2, d3, e0, e1, e2, e3;   // slice B weights
};

__device__ __forceinline__ Batch load_batch(
    const float4* W0, const float4* W1, const float4* W2, const float4* W3,
    const float4* R0, const float4* R1, const float4* R2, const float4* R3,
    const float4* xv4, const float4* hv4, int ka, int kb)
{
    Batch b;
    b.x0 = __ldg(xv4 + ka);
    b.h0 = __ldg(hv4 + ka);
    b.x1 = __ldg(xv4 + kb);
    b.h1 = __ldg(hv4 + kb);
    b.a0 = __ldcs(W0 + ka);
    b.a1 = __ldcs(W1 + ka);
    b.a2 = __ldcs(W2 + ka);
    b.a3 = __ldcs(W3 + ka);
    b.c0 = __ldcs(R0 + ka);
    b.c1 = __ldcs(R1 + ka);
    b.c2 = __ldcs(R2 + ka);
    b.c3 = __ldcs(R3 + ka);
    b.d0 = __ldcs(W0 + kb);
    b.d1 = __ldcs(W1 + kb);
    b.d2 = __ldcs(W2 + kb);
    b.d3 = __ldcs(W3 + kb);
    b.e0 = __ldcs(R0 + kb);
    b.e1 = __ldcs(R1 + kb);
    b.e2 = __ldcs(R2 + kb);
    b.e3 = __ldcs(R3 + kb);
    return b;
}

__device__ __forceinline__ void fma_batch(const Batch& b, float* A, float* B)
{
    A[0] += b.a0.x * b.x0.x + b.a0.y * b.x0.y + b.a0.z * b.x0.z + b.a0.w * b.x0.w;
    A[1] += b.a1.x * b.x0.x + b.a1.y * b.x0.y + b.a1.z * b.x0.z + b.a1.w * b.x0.w;
    A[2] += b.a2.x * b.x0.x + b.a2.y * b.x0.y + b.a2.z * b.x0.z + b.a2.w * b.x0.w;
    A[3] += b.a3.x * b.x0.x + b.a3.y * b.x0.y + b.a3.z * b.x0.z + b.a3.w * b.x0.w;
    A[4] += b.c0.x * b.h0.x + b.c0.y * b.h0.y + b.c0.z * b.h0.z + b.c0.w * b.h0.w;
    A[5] += b.c1.x * b.h0.x + b.c1.y * b.h0.y + b.c1.z * b.h0.z + b.c1.w * b.h0.w;
    A[6] += b.c2.x * b.h0.x + b.c2.y * b.h0.y + b.c2.z * b.h0.z + b.c2.w * b.h0.w;
    A[7] += b.c3.x * b.h0.x + b.c3.y * b.h0.y + b.c3.z * b.h0.z + b.c3.w * b.h0.w;

    B[0] += b.d0.x * b.x1.x + b.d0.y * b.x1.y + b.d0.z * b.x1.z + b.d0.w * b.x1.w;
    B[1] += b.d1.x * b.x1.x + b.d1.y * b.x1.y + b.d1.z * b.x1.z + b.d1.w * b.x1.w;
    B[2] += b.d2.x * b.x1.x + b.d2.y * b.x1.y + b.d2.z * b.x1.z + b.d2.w * b.x1.w;
    B[3] += b.d3.x * b.x1.x + b.d3.y * b.x1.y + b.d3.z * b.x1.z + b.d3.w * b.x1.w;
    B[4] += b.e0.x * b.h1.x + b.e0.y * b.h1.y + b.e0.z * b.h1.z + b.e0.w * b.h1.w;
    B[5] += b.e1.x * b.h1.x + b.e1.y * b.h1.y + b.e1.z * b.h1.z + b.e1.w * b.h1.w;
    B[6] += b.e2.x * b.h1.x + b.e2.y * b.h1.y + b.e2.z * b.h1.z + b.e2.w * b.h1.w;
    B[7] += b.e3.x * b.h1.x + b.e3.y * b.h1.y + b.e3.z * b.h1.z + b.e3.w * b.h1.w;
}

// Folded multi-value warp reduction: 8 gate sums in 9 shuffles.
// On exit, lanes with (lane&3)==0 hold gate g = bit2(lane)*1 + bit3(lane)*2 + bit4(lane)*4.
__device__ __forceinline__ void warp_reduce8_store(const float* acc, float* dst, int lane)
{
    const bool lo16 = (lane & 16) == 0;
    float v[4];
#pragma unroll
    for (int g = 0; g < 4; ++g) {
        float keep = lo16 ? acc[g]     : acc[g + 4];
        float send = lo16 ? acc[g + 4] : acc[g];
        float recv = __shfl_xor_sync(0xFFFFFFFFu, send, 16);
        v[g] = keep + recv;
    }
    const bool lo8 = (lane & 8) == 0;
    float u[2];
#pragma unroll
    for (int g = 0; g < 2; ++g) {
        float keep = lo8 ? v[g]     : v[g + 2];
        float send = lo8 ? v[g + 2] : v[g];
        float recv = __shfl_xor_sync(0xFFFFFFFFu, send, 8);
        u[g] = keep + recv;
    }
    const bool lo4 = (lane & 4) == 0;
    float keep = lo4 ? u[0] : u[1];
    float send = lo4 ? u[1] : u[0];
    float w = keep + __shfl_xor_sync(0xFFFFFFFFu, send, 4);
    w += __shfl_xor_sync(0xFFFFFFFFu, w, 2);
    w += __shfl_xor_sync(0xFFFFFFFFu, w, 1);

    const int g = ((lane >> 2) & 1) | (((lane >> 3) & 1) << 1) | (((lane >> 4) & 1) << 2);
    if ((lane & 3) == 0) dst[g] = w;
}

__global__ __launch_bounds__(TPB, 2) void slstm_row2_kernel(
    const float* __restrict__ x,
    const float* __restrict__ h_prev,
    const float* __restrict__ c_prev,
    const float* __restrict__ n_prev,
    const float* __restrict__ m_prev,
    const float* __restrict__ w_i,
    const float* __restrict__ w_f,
    const float* __restrict__ w_o,
    const float* __restrict__ w_z,
    const float* __restrict__ r_i,
    const float* __restrict__ r_f,
    const float* __restrict__ r_o,
    const float* __restrict__ r_z,
    const float* __restrict__ b_i,
    const float* __restrict__ b_f,
    const float* __restrict__ b_o,
    const float* __restrict__ b_z,
    float* __restrict__ out)
{
    const int tid  = threadIdx.x;
    const int lane = tid & 31;
    const int warp = tid >> 5;

    const int row0 = blockIdx.x;
    const int row1 = blockIdx.x + GRID;

    const float4* xv4 = (const float4*)x;
    const float4* hv4 = (const float4*)h_prev;

    const int k0 = tid;
    const int k1 = TPB + tid;
    const int k2 = 2 * TPB + tid;
    const int k3 = 3 * TPB + tid;

    __shared__ float red[ROWS_PER_CTA][NWARP][8];
    __shared__ float tot[ROWS_PER_CTA][8];

    const size_t o0 = (size_t)row0 * IDIM;
    const size_t o1 = (size_t)row1 * IDIM;

    // ---------------- row 0 ----------------
    float A0[8], B0[8];
#pragma unroll
    for (int g = 0; g < 8; ++g) { A0[g] = 0.0f; B0[g] = 0.0f; }
    {
        Batch b = load_batch((const float4*)(w_i + o0), (const float4*)(w_f + o0),
                             (const float4*)(w_o + o0), (const float4*)(w_z + o0),
                             (const float4*)(r_i + o0), (const float4*)(r_f + o0),
                             (const float4*)(r_o + o0), (const float4*)(r_z + o0),
                             xv4, hv4, k0, k1);
        fma_batch(b, A0, B0);
    }
    {
        Batch b = load_batch((const float4*)(w_i + o0), (const float4*)(w_f + o0),
                             (const float4*)(w_o + o0), (const float4*)(w_z + o0),
                             (const float4*)(r_i + o0), (const float4*)(r_f + o0),
                             (const float4*)(r_o + o0), (const float4*)(r_z + o0),
                             xv4, hv4, k2, k3);
        fma_batch(b, A0, B0);
    }
    float acc0[8];
#pragma unroll
    for (int g = 0; g < 8; ++g) acc0[g] = A0[g] + B0[g];

    // ---------------- row 1: issue first batch BEFORE reducing row 0 ----------------
    float A1[8], B1[8];
#pragma unroll
    for (int g = 0; g < 8; ++g) { A1[g] = 0.0f; B1[g] = 0.0f; }

    Batch b10 = load_batch((const float4*)(w_i + o1), (const float4*)(w_f + o1),
                           (const float4*)(w_o + o1), (const float4*)(w_z + o1),
                           (const float4*)(r_i + o1), (const float4*)(r_f + o1),
                           (const float4*)(r_o + o1), (const float4*)(r_z + o1),
                           xv4, hv4, k0, k1);

    // row-0 reduction executes under row-1's load latency
    warp_reduce8_store(acc0, red[0][warp], lane);

    fma_batch(b10, A1, B1);
    {
        Batch b = load_batch((const float4*)(w_i + o1), (const float4*)(w_f + o1),
                             (const float4*)(w_o + o1), (const float4*)(w_z + o1),
                             (const float4*)(r_i + o1), (const float4*)(r_f + o1),
                             (const float4*)(r_o + o1), (const float4*)(r_z + o1),
                             xv4, hv4, k2, k3);
        fma_batch(b, A1, B1);
    }
    float acc1[8];
#pragma unroll
    for (int g = 0; g < 8; ++g) acc1[g] = A1[g] + B1[g];
    warp_reduce8_store(acc1, red[1][warp], lane);

    __syncthreads();

    // cross-warp totals: thread t<16 -> (row = t>>3, gate = t&7)
    if (tid < 16) {
        const int rr = tid >> 3;
        const int g  = tid & 7;
        float s = 0.0f;
#pragma unroll
        for (int w = 0; w < NWARP; ++w) s += red[rr][w][g];
        tot[rr][g] = s;
    }
    __syncwarp(0xFFFFFFFFu);

    // gating: thread t<2 handles row t
    if (tid < ROWS_PER_CTA) {
        const int r = blockIdx.x + tid * GRID;

        float i_t = tot[tid][0] + tot[tid][4] + __ldg(b_i + r);
        float f_t = tot[tid][1] + tot[tid][5] + __ldg(b_f + r);
        float o_t = tot[tid][2] + tot[tid][6] + __ldg(b_o + r);
        float z_t = tot[tid][3] + tot[tid][7] + __ldg(b_z + r);

        float mp = __ldg(m_prev + r);
        float cp = __ldg(c_prev + r);
        float np = __ldg(n_prev + r);

        // stable log_sigmoid(f) = min(f,0) - log1p(exp(-|f|))
        float log_f = fminf(f_t, 0.0f) - log1pf(expf(-fabsf(f_t)));
        float m_t = fmaxf(log_f + mp, i_t);
        float i_p = expf(i_t - m_t);
        float f_p = expf(log_f + mp - m_t);
        float c_t = f_p * cp + i_p * tanhf(z_t);
        float n_t = f_p * np + i_p;
        float sig_o = 1.0f / (1.0f + expf(-o_t));
        float h_t = sig_o * tanhf(c_t / n_t);

        out[r]            = h_t;
        out[HDIM + r]     = c_t;
        out[2 * HDIM + r] = n_t;
        out[3 * HDIM + r] = m_t;
    }
}

extern "C" void kernel_launch(void* const* d_in, const int* in_sizes, int n_in,
                              void* d_out, int out_size)
{
    const float* x      = (const float*)d_in[0];
    const float* h_prev = (const float*)d_in[1];
    const float* c_prev = (const float*)d_in[2];
    const float* n_prev = (const float*)d_in[3];
    const float* m_prev = (const float*)d_in[4];
    const float* w_i    = (const float*)d_in[5];
    const float* w_f    = (const float*)d_in[6];
    const float* w_o    = (const float*)d_in[7];
    const float* w_z    = (const float*)d_in[8];
    const float* r_i    = (const float*)d_in[9];
    const float* r_f    = (const float*)d_in[10];
    const float* r_o    = (const float*)d_in[11];
    const float* r_z    = (const float*)d_in[12];
    const float* b_i    = (const float*)d_in[13];
    const float* b_f    = (const float*)d_in[14];
    const float* b_o    = (const float*)d_in[15];
    const float* b_z    = (const float*)d_in[16];
    float* out = (float*)d_out;

    slstm_row2_kernel<<<GRID, TPB>>>(x, h_prev, c_prev, n_prev, m_prev,
                                     w_i, w_f, w_o, w_z,
                                     r_i, r_f, r_o, r_z,
                                     b_i, b_f, b_o, b_z, out);
}